// round 4
// baseline (speedup 1.0000x reference)
#include <cuda_runtime.h>

#define SQ 2048
#define HID 1024
#define HEADS 16
#define HD 64
#define BSZ 2
#define BH (BSZ*HEADS)
#define ROWS_TOT (BSZ*SQ)

// scratch (allocation-free: device globals)
__device__ float g_q[BH*SQ*HD];
__device__ float g_k[BH*SQ*HD];
__device__ float g_v[BH*SQ*HD];
__device__ float g_vp[BH*SQ*HD];
__device__ float g_att[ROWS_TOT*HID];
__device__ float g_mod[HID];
__device__ float g_cs[SQ];
__device__ float g_sn[SQ];

__device__ __forceinline__ float tf32r(float x) {
    float y;
    asm("cvt.rna.tf32.f32 %0, %1;" : "=f"(y) : "f"(x));
    return y;
}
__device__ __forceinline__ unsigned fu(float x) { return __float_as_uint(x); }

#define MMA_TF32(d, a0, a1, a2, a3, b0, b1)                                        \
    asm volatile(                                                                   \
        "mma.sync.aligned.m16n8k8.row.col.f32.tf32.tf32.f32 "                       \
        "{%0,%1,%2,%3},{%4,%5,%6,%7},{%8,%9},{%0,%1,%2,%3};"                        \
        : "+f"(d[0]), "+f"(d[1]), "+f"(d[2]), "+f"(d[3])                            \
        : "r"(a0), "r"(a1), "r"(a2), "r"(a3), "r"(b0), "r"(b1))

// ---------------------------------------------------------------- prep
__global__ void prep_kernel(const float* __restrict__ phase,
                            const float* __restrict__ amp) {
    int i = blockIdx.x * 256 + threadIdx.x;
    if (i < HID) g_mod[i] = cosf(phase[i]) * amp[i];
    if (i < SQ) {
        float a = 6.283185307179586f * (float)i / (float)SQ;
        g_cs[i] = cosf(a);
        g_sn[i] = sinf(a);
    }
}

// ---------------------------------------------------------------- V roll
__global__ void roll_kernel() {
    int idx = blockIdx.x * 256 + threadIdx.x;  // float4 index
    if (idx >= BH * SQ * (HD / 4)) return;
    int d4 = idx & 15;
    int rest = idx >> 4;
    int s = rest & (SQ - 1);
    int bh = rest >> 11;
    int s2 = (s + 1) & (SQ - 1);
    const float4* v = (const float4*)g_v;
    float4 a = v[(((size_t)bh * SQ + s) << 4) + d4];
    float4 b = v[(((size_t)bh * SQ + s2) << 4) + d4];
    float4 o;
    const float r = 0.7071067811865476f;
    o.x = (a.x + b.x) * r;
    o.y = (a.y + b.y) * r;
    o.z = (a.z + b.z) * r;
    o.w = (a.w + b.w) * r;
    ((float4*)g_vp)[idx] = o;
}

// ---------------------------------------------------------------- TF32 GEMM (QKV)
// C = X[4096,1024] @ W[1024,1024], tile 128x128, kblock 32, 8 warps 2m x 4n.
// A stored in paired-k layout: within each 8-k group, order [k0,k4,k1,k5,k2,k6,k3,k7]
#define LDA 40
#define LDB 136
#define GEMM_SMEM ((2*128*LDA + 2*32*LDB) * 4)

__device__ __forceinline__ void store_a_paired(float* dst, const float4* pa) {
    float4 y0 = {tf32r(pa[0].x), tf32r(pa[1].x), tf32r(pa[0].y), tf32r(pa[1].y)};
    float4 y1 = {tf32r(pa[0].z), tf32r(pa[1].z), tf32r(pa[0].w), tf32r(pa[1].w)};
    float4 y2 = {tf32r(pa[2].x), tf32r(pa[3].x), tf32r(pa[2].y), tf32r(pa[3].y)};
    float4 y3 = {tf32r(pa[2].z), tf32r(pa[3].z), tf32r(pa[2].w), tf32r(pa[3].w)};
    *(float4*)(dst + 0) = y0;
    *(float4*)(dst + 4) = y1;
    *(float4*)(dst + 8) = y2;
    *(float4*)(dst + 12) = y3;
}

__global__ __launch_bounds__(256, 2) void qkv_gemm(const float* __restrict__ X,
                                                   const float* __restrict__ Wq,
                                                   const float* __restrict__ Wk,
                                                   const float* __restrict__ Wv) {
    extern __shared__ float smg[];
    float* As = smg;                  // [2][128*LDA] paired-k
    float* Bs = smg + 2 * 128 * LDA;  // [2][32*LDB]

    int mode = blockIdx.z;
    const float* W = (mode == 0) ? Wq : (mode == 1) ? Wk : Wv;
    float* dst = (mode == 0) ? g_q : (mode == 1) ? g_k : g_v;

    int bn = blockIdx.x, bm = blockIdx.y;
    int tid = threadIdx.x, lane = tid & 31, w = tid >> 5;
    int wm = w >> 2, wn = w & 3;
    int r = lane >> 2, c = lane & 3;

    int arow = tid >> 1, acol0 = (tid & 1) * 16;
    int brow = tid >> 3, bcol0 = (tid & 7) * 16;
    const float* Ag = X + (size_t)(bm * 128 + arow) * HID + acol0;
    const float* Bg = W + (size_t)brow * HID + bn * 128 + bcol0;

    float4 pa[4], pb[4];
#pragma unroll
    for (int q = 0; q < 4; q++) {
        pa[q] = *(const float4*)(Ag + q * 4);
        pb[q] = *(const float4*)(Bg + q * 4);
    }
    store_a_paired(&As[arow * LDA + acol0], pa);
#pragma unroll
    for (int q = 0; q < 4; q++) {
        float4 tb = {tf32r(pb[q].x), tf32r(pb[q].y), tf32r(pb[q].z), tf32r(pb[q].w)};
        *(float4*)&Bs[brow * LDB + bcol0 + q * 4] = tb;
    }
    __syncthreads();

    float acc[4][4][4];
#pragma unroll
    for (int i = 0; i < 4; i++)
#pragma unroll
        for (int j = 0; j < 4; j++)
#pragma unroll
            for (int e = 0; e < 4; e++) acc[i][j][e] = 0.f;

    for (int kb = 0; kb < 32; kb++) {
        const float* Ac = As + (kb & 1) * (128 * LDA);
        const float* Bc = Bs + (kb & 1) * (32 * LDB);
        if (kb < 31) {
            const float* Ag2 = Ag + (kb + 1) * 32;
            const float* Bg2 = Bg + (size_t)(kb + 1) * 32 * HID;
#pragma unroll
            for (int q = 0; q < 4; q++) {
                pa[q] = *(const float4*)(Ag2 + q * 4);
                pb[q] = *(const float4*)(Bg2 + q * 4);
            }
        }
#pragma unroll
        for (int kk = 0; kk < 4; kk++) {
            unsigned a[4][4], b[4][2];
#pragma unroll
            for (int i = 0; i < 4; i++) {
                const float* p = Ac + (wm * 64 + i * 16 + r) * LDA + kk * 8 + 2 * c;
                float2 lo = *(const float2*)p;
                float2 hi = *(const float2*)(p + 8 * LDA);
                a[i][0] = fu(lo.x);
                a[i][1] = fu(hi.x);
                a[i][2] = fu(lo.y);
                a[i][3] = fu(hi.y);
            }
#pragma unroll
            for (int j = 0; j < 4; j++) {
                const float* p = Bc + (kk * 8 + c) * LDB + wn * 32 + j * 8 + r;
                b[j][0] = fu(p[0]);
                b[j][1] = fu(p[4 * LDB]);
            }
#pragma unroll
            for (int i = 0; i < 4; i++)
#pragma unroll
                for (int j = 0; j < 4; j++)
                    MMA_TF32(acc[i][j], a[i][0], a[i][1], a[i][2], a[i][3],
                             b[j][0], b[j][1]);
        }
        if (kb < 31) {
            float* An = As + ((kb + 1) & 1) * (128 * LDA);
            float* Bn = Bs + ((kb + 1) & 1) * (32 * LDB);
            store_a_paired(&An[arow * LDA + acol0], pa);
#pragma unroll
            for (int q = 0; q < 4; q++) {
                float4 tb = {tf32r(pb[q].x), tf32r(pb[q].y), tf32r(pb[q].z), tf32r(pb[q].w)};
                *(float4*)&Bn[brow * LDB + bcol0 + q * 4] = tb;
            }
            __syncthreads();
        }
    }

    // epilogue: mod scale (q also 1/8), scatter to [B,H,S,D]
    float sc = (mode == 0) ? 0.125f : 1.0f;
#pragma unroll
    for (int i = 0; i < 4; i++) {
#pragma unroll
        for (int ro = 0; ro < 2; ro++) {
            int grow = bm * 128 + wm * 64 + i * 16 + r + ro * 8;
            int bb = grow >> 11;
            int ss = grow & 2047;
#pragma unroll
            for (int j = 0; j < 4; j++) {
                int col = bn * 128 + wn * 32 + j * 8 + 2 * c;
                int hh = col >> 6;
                int dd = col & 63;
                float m0v = g_mod[col] * sc;
                float m1v = g_mod[col + 1] * sc;
                float2 v;
                v.x = acc[i][j][ro * 2 + 0] * m0v;
                v.y = acc[i][j][ro * 2 + 1] * m1v;
                *(float2*)&dst[(((size_t)(bb * HEADS + hh) * SQ + ss) * HD + dd)] = v;
            }
        }
    }
}

// ---------------------------------------------------------------- TF32 GEMM (out)
__global__ __launch_bounds__(256, 2) void out_gemm(const float* __restrict__ W,
                                                   float* __restrict__ C) {
    extern __shared__ float smg[];
    float* As = smg;
    float* Bs = smg + 2 * 128 * LDA;

    int bn = blockIdx.x, bm = blockIdx.y;
    int tid = threadIdx.x, lane = tid & 31, w = tid >> 5;
    int wm = w >> 2, wn = w & 3;
    int r = lane >> 2, c = lane & 3;

    int arow = tid >> 1, acol0 = (tid & 1) * 16;
    int brow = tid >> 3, bcol0 = (tid & 7) * 16;
    const float* Ag = g_att + (size_t)(bm * 128 + arow) * HID + acol0;
    const float* Bg = W + (size_t)brow * HID + bn * 128 + bcol0;

    float4 pa[4], pb[4];
#pragma unroll
    for (int q = 0; q < 4; q++) {
        pa[q] = *(const float4*)(Ag + q * 4);
        pb[q] = *(const float4*)(Bg + q * 4);
    }
    store_a_paired(&As[arow * LDA + acol0], pa);
#pragma unroll
    for (int q = 0; q < 4; q++) {
        float4 tb = {tf32r(pb[q].x), tf32r(pb[q].y), tf32r(pb[q].z), tf32r(pb[q].w)};
        *(float4*)&Bs[brow * LDB + bcol0 + q * 4] = tb;
    }
    __syncthreads();

    float acc[4][4][4];
#pragma unroll
    for (int i = 0; i < 4; i++)
#pragma unroll
        for (int j = 0; j < 4; j++)
#pragma unroll
            for (int e = 0; e < 4; e++) acc[i][j][e] = 0.f;

    for (int kb = 0; kb < 32; kb++) {
        const float* Ac = As + (kb & 1) * (128 * LDA);
        const float* Bc = Bs + (kb & 1) * (32 * LDB);
        if (kb < 31) {
            const float* Ag2 = Ag + (kb + 1) * 32;
            const float* Bg2 = Bg + (size_t)(kb + 1) * 32 * HID;
#pragma unroll
            for (int q = 0; q < 4; q++) {
                pa[q] = *(const float4*)(Ag2 + q * 4);
                pb[q] = *(const float4*)(Bg2 + q * 4);
            }
        }
#pragma unroll
        for (int kk = 0; kk < 4; kk++) {
            unsigned a[4][4], b[4][2];
#pragma unroll
            for (int i = 0; i < 4; i++) {
                const float* p = Ac + (wm * 64 + i * 16 + r) * LDA + kk * 8 + 2 * c;
                float2 lo = *(const float2*)p;
                float2 hi = *(const float2*)(p + 8 * LDA);
                a[i][0] = fu(lo.x);
                a[i][1] = fu(hi.x);
                a[i][2] = fu(lo.y);
                a[i][3] = fu(hi.y);
            }
#pragma unroll
            for (int j = 0; j < 4; j++) {
                const float* p = Bc + (kk * 8 + c) * LDB + wn * 32 + j * 8 + r;
                b[j][0] = fu(p[0]);
                b[j][1] = fu(p[4 * LDB]);
            }
#pragma unroll
            for (int i = 0; i < 4; i++)
#pragma unroll
                for (int j = 0; j < 4; j++)
                    MMA_TF32(acc[i][j], a[i][0], a[i][1], a[i][2], a[i][3],
                             b[j][0], b[j][1]);
        }
        if (kb < 31) {
            float* An = As + ((kb + 1) & 1) * (128 * LDA);
            float* Bn = Bs + ((kb + 1) & 1) * (32 * LDB);
            store_a_paired(&An[arow * LDA + acol0], pa);
#pragma unroll
            for (int q = 0; q < 4; q++) {
                float4 tb = {tf32r(pb[q].x), tf32r(pb[q].y), tf32r(pb[q].z), tf32r(pb[q].w)};
                *(float4*)&Bn[brow * LDB + bcol0 + q * 4] = tb;
            }
            __syncthreads();
        }
    }

#pragma unroll
    for (int i = 0; i < 4; i++) {
#pragma unroll
        for (int ro = 0; ro < 2; ro++) {
            int grow = bm * 128 + wm * 64 + i * 16 + r + ro * 8;
#pragma unroll
            for (int j = 0; j < 4; j++) {
                int col = bn * 128 + wn * 32 + j * 8 + 2 * c;
                float2 v;
                v.x = acc[i][j][ro * 2 + 0];
                v.y = acc[i][j][ro * 2 + 1];
                *(float2*)&C[(size_t)grow * HID + col] = v;
            }
        }
    }
}

// ---------------------------------------------------------------- flash attention (TF32 mma, v3)
// grid (16,16,2), 256 thr = 8 warps; warp w owns rows [w*16, w*16+16).
// M-tile 128, N-tile 64 per iteration. 2 CTAs/SM.
// Paired-k layouts for Q, K, P; V stored transposed [d][n-paired].
#define LDQ 72
#define LDK 72
#define LDVT 72
#define LDP 72
#define NT 64
#define ATT_SMEM ((128*LDQ + NT*LDK + NT*LDVT + 128*LDP + 2*NT) * 4)

__global__ __launch_bounds__(256, 2) void attn_kernel() {
    extern __shared__ float sma[];
    float* Qs = sma;                  // [128][LDQ] paired-k
    float* Ks = Qs + 128 * LDQ;       // [64][LDK] paired-k
    float* Vt = Ks + NT * LDK;        // [64 d][LDVT] n-paired
    float* Ps = Vt + NT * LDVT;       // [128][LDP] paired-k (warp-private rows)
    float* cjs = Ps + 128 * LDP;      // [64]
    float* sjs = cjs + NT;            // [64]

    int m0 = blockIdx.x * 128;
    int h = blockIdx.y, b = blockIdx.z;
    int bh = b * HEADS + h;
    const float* Qg = g_q + (size_t)bh * SQ * HD;
    const float* Kg = g_k + (size_t)bh * SQ * HD;
    const float* Vg = g_vp + (size_t)bh * SQ * HD;

    int tid = threadIdx.x, lane = tid & 31, w = tid >> 5;
    int r = lane >> 2, c = lane & 3;

    // load Q tile once (paired-k): row = tid>>1, d-half = (tid&1)*32
    {
        int row = tid >> 1;
        int dh = (tid & 1) * 32;
        const float* src = Qg + (size_t)(m0 + row) * HD + dh;
        float* drow = Qs + row * LDQ + dh;
#pragma unroll
        for (int cc = 0; cc < 4; cc++) {
            float4 x0 = *(const float4*)(src + cc * 8);
            float4 x1 = *(const float4*)(src + cc * 8 + 4);
            float4 y0 = {tf32r(x0.x), tf32r(x1.x), tf32r(x0.y), tf32r(x1.y)};
            float4 y1 = {tf32r(x0.z), tf32r(x1.z), tf32r(x0.w), tf32r(x1.w)};
            *(float4*)(drow + cc * 8) = y0;
            *(float4*)(drow + cc * 8 + 4) = y1;
        }
    }

    // per-thread row trig + online-softmax state
    float cmv[2], smv[2], ms[2], ls[2];
#pragma unroll
    for (int ro = 0; ro < 2; ro++) {
        int row = m0 + w * 16 + r + ro * 8;
        cmv[ro] = g_cs[row];
        smv[ro] = g_sn[row];
        ms[ro] = -1e30f;
        ls[ro] = 0.f;
    }
    float o[8][4];
#pragma unroll
    for (int j = 0; j < 8; j++)
#pragma unroll
        for (int e = 0; e < 4; e++) o[j][e] = 0.f;

    for (int n0 = 0; n0 < SQ; n0 += NT) {
        __syncthreads();  // previous iter's reads of Ks/Vt done (also Q store on iter 0)

        // K tile (paired-k): row = tid>>2, 2 chunk-sets
        {
            int krow = tid >> 2;
            int kcb = (tid & 3) * 8;
            const float* src = Kg + (size_t)(n0 + krow) * HD;
            float* drow = Ks + krow * LDK;
#pragma unroll
            for (int hh = 0; hh < 2; hh++) {
                int db = kcb + hh * 32;
                float4 x0 = *(const float4*)(src + db);
                float4 x1 = *(const float4*)(src + db + 4);
                float4 y0 = {tf32r(x0.x), tf32r(x1.x), tf32r(x0.y), tf32r(x1.y)};
                float4 y1 = {tf32r(x0.z), tf32r(x1.z), tf32r(x0.w), tf32r(x1.w)};
                *(float4*)(drow + db) = y0;
                *(float4*)(drow + db + 4) = y1;
            }
        }
        // V tile transposed + n-paired: d = tid&63, n-groups (tid>>6), (tid>>6)+4
        {
            int d = tid & 63;
            int ng0 = tid >> 6;
            const float* src = Vg + (size_t)n0 * HD + d;
#pragma unroll
            for (int gg = 0; gg < 2; gg++) {
                int ng = ng0 + gg * 4;
                const float* s8 = src + (size_t)(ng * 8) * HD;
                float v0 = s8[0 * HD], v4 = s8[4 * HD];
                float v1 = s8[1 * HD], v5 = s8[5 * HD];
                float v2 = s8[2 * HD], v6 = s8[6 * HD];
                float v3 = s8[3 * HD], v7 = s8[7 * HD];
                float4 y0 = {tf32r(v0), tf32r(v4), tf32r(v1), tf32r(v5)};
                float4 y1 = {tf32r(v2), tf32r(v6), tf32r(v3), tf32r(v7)};
                *(float4*)(Vt + d * LDVT + ng * 8) = y0;
                *(float4*)(Vt + d * LDVT + ng * 8 + 4) = y1;
            }
        }
        if (tid < NT) {
            cjs[tid] = g_cs[n0 + tid];
            sjs[tid] = g_sn[n0 + tid];
        }
        __syncthreads();

        // S = Q K^T : warp tile m16 x n64
        float s[8][4];
#pragma unroll
        for (int j = 0; j < 8; j++)
#pragma unroll
            for (int e = 0; e < 4; e++) s[j][e] = 0.f;

#pragma unroll
        for (int kk = 0; kk < 8; kk++) {
            float2 qlo = *(const float2*)&Qs[(w * 16 + r) * LDQ + kk * 8 + 2 * c];
            float2 qhi = *(const float2*)&Qs[(w * 16 + r + 8) * LDQ + kk * 8 + 2 * c];
            unsigned a0 = fu(qlo.x), a1 = fu(qhi.x), a2 = fu(qlo.y), a3 = fu(qhi.y);
#pragma unroll
            for (int j = 0; j < 8; j++) {
                float2 kb = *(const float2*)&Ks[(j * 8 + r) * LDK + kk * 8 + 2 * c];
                MMA_TF32(s[j], a0, a1, a2, a3, fu(kb.x), fu(kb.y));
            }
        }

        // interference modulation
#pragma unroll
        for (int j = 0; j < 8; j++) {
            float2 cjp = *(const float2*)&cjs[j * 8 + 2 * c];
            float2 sjp = *(const float2*)&sjs[j * 8 + 2 * c];
            s[j][0] *= (cmv[0] * cjp.x + smv[0] * sjp.x);
            s[j][1] *= (cmv[0] * cjp.y + smv[0] * sjp.y);
            s[j][2] *= (cmv[1] * cjp.x + smv[1] * sjp.x);
            s[j][3] *= (cmv[1] * cjp.y + smv[1] * sjp.y);
        }

        // online softmax per row group
#pragma unroll
        for (int ro = 0; ro < 2; ro++) {
            float mx = -1e30f;
#pragma unroll
            for (int j = 0; j < 8; j++)
                mx = fmaxf(mx, fmaxf(s[j][ro * 2], s[j][ro * 2 + 1]));
            mx = fmaxf(mx, __shfl_xor_sync(0xffffffffu, mx, 1));
            mx = fmaxf(mx, __shfl_xor_sync(0xffffffffu, mx, 2));
            float mn = fmaxf(ms[ro], mx);
            float al = __expf(ms[ro] - mn);
            float sum = 0.f;
#pragma unroll
            for (int j = 0; j < 8; j++) {
                float p0 = __expf(s[j][ro * 2] - mn);
                float p1 = __expf(s[j][ro * 2 + 1] - mn);
                s[j][ro * 2] = p0;
                s[j][ro * 2 + 1] = p1;
                sum += p0 + p1;
            }
            sum += __shfl_xor_sync(0xffffffffu, sum, 1);
            sum += __shfl_xor_sync(0xffffffffu, sum, 2);
            ls[ro] = ls[ro] * al + sum;
            ms[ro] = mn;
#pragma unroll
            for (int j2 = 0; j2 < 8; j2++) {
                o[j2][ro * 2] *= al;
                o[j2][ro * 2 + 1] *= al;
            }
        }

        // write P (warp-private rows, paired-k positions)
        {
            int p0 = (c < 2) ? 4 * c : 4 * c - 7;
            int p1 = (c < 2) ? 4 * c + 2 : 4 * c - 5;
            float* pr = Ps + (w * 16 + r) * LDP;
#pragma unroll
            for (int j = 0; j < 8; j++) {
                float* pj = pr + j * 8;
                pj[p0] = tf32r(s[j][0]);
                pj[p1] = tf32r(s[j][1]);
                pj[8 * LDP + p0] = tf32r(s[j][2]);
                pj[8 * LDP + p1] = tf32r(s[j][3]);
            }
        }
        __syncwarp();

        // O += P @ V' : warp tile m16 x n64, k = NT
#pragma unroll
        for (int kk = 0; kk < 8; kk++) {
            float2 plo = *(const float2*)&Ps[(w * 16 + r) * LDP + kk * 8 + 2 * c];
            float2 phi = *(const float2*)&Ps[(w * 16 + r + 8) * LDP + kk * 8 + 2 * c];
            unsigned a0 = fu(plo.x), a1 = fu(phi.x), a2 = fu(plo.y), a3 = fu(phi.y);
#pragma unroll
            for (int j2 = 0; j2 < 8; j2++) {
                float2 bv = *(const float2*)&Vt[(j2 * 8 + r) * LDVT + kk * 8 + 2 * c];
                MMA_TF32(o[j2], a0, a1, a2, a3, fu(bv.x), fu(bv.y));
            }
        }
        __syncwarp();  // P reads done before next iter's P stores
    }

    // epilogue: normalize + write [B,S,H*D]
#pragma unroll
    for (int ro = 0; ro < 2; ro++) {
        float inv = 1.0f / ls[ro];
        int row = m0 + w * 16 + r + ro * 8;
#pragma unroll
        for (int j2 = 0; j2 < 8; j2++) {
            int col = j2 * 8 + 2 * c;
            float2 v;
            v.x = o[j2][ro * 2] * inv;
            v.y = o[j2][ro * 2 + 1] * inv;
            *(float2*)&g_att[((size_t)(b * SQ + row)) * HID + h * HD + col] = v;
        }
    }
}

// ---------------------------------------------------------------- launch
extern "C" void kernel_launch(void* const* d_in, const int* in_sizes, int n_in,
                              void* d_out, int out_size) {
    const float* x     = (const float*)d_in[0];
    const float* Wq    = (const float*)d_in[1];
    const float* Wk    = (const float*)d_in[2];
    const float* Wv    = (const float*)d_in[3];
    const float* Wo    = (const float*)d_in[4];
    const float* phase = (const float*)d_in[5];
    const float* amp   = (const float*)d_in[6];
    float* out = (float*)d_out;

    cudaFuncSetAttribute(qkv_gemm, cudaFuncAttributeMaxDynamicSharedMemorySize, GEMM_SMEM);
    cudaFuncSetAttribute(out_gemm, cudaFuncAttributeMaxDynamicSharedMemorySize, GEMM_SMEM);
    cudaFuncSetAttribute(attn_kernel, cudaFuncAttributeMaxDynamicSharedMemorySize, ATT_SMEM);

    prep_kernel<<<8, 256>>>(phase, amp);
    qkv_gemm<<<dim3(8, 32, 3), 256, GEMM_SMEM>>>(x, Wq, Wk, Wv);
    roll_kernel<<<(BH * SQ * (HD / 4)) / 256, 256>>>();
    attn_kernel<<<dim3(16, 16, 2), 256, ATT_SMEM>>>();
    out_gemm<<<dim3(8, 32), 256, GEMM_SMEM>>>(Wo, out);
}

// round 5
// speedup vs baseline: 1.0024x; 1.0024x over previous
#include <cuda_runtime.h>

#define SQ 2048
#define HID 1024
#define HEADS 16
#define HD 64
#define BSZ 2
#define BH (BSZ*HEADS)
#define ROWS_TOT (BSZ*SQ)

// scratch (allocation-free: device globals)
__device__ float g_q[BH*SQ*HD];
__device__ float g_k[BH*SQ*HD];
__device__ float g_v[BH*SQ*HD];
__device__ float g_vp[BH*SQ*HD];
__device__ float g_att[ROWS_TOT*HID];
__device__ float g_mod[HID];
__device__ float g_cs[SQ];
__device__ float g_sn[SQ];

__device__ __forceinline__ float tf32r(float x) {
    float y;
    asm("cvt.rna.tf32.f32 %0, %1;" : "=f"(y) : "f"(x));
    return y;
}
__device__ __forceinline__ unsigned fu(float x) { return __float_as_uint(x); }

#define MMA_TF32(d, a0, a1, a2, a3, b0, b1)                                        \
    asm volatile(                                                                   \
        "mma.sync.aligned.m16n8k8.row.col.f32.tf32.tf32.f32 "                       \
        "{%0,%1,%2,%3},{%4,%5,%6,%7},{%8,%9},{%0,%1,%2,%3};"                        \
        : "+f"(d[0]), "+f"(d[1]), "+f"(d[2]), "+f"(d[3])                            \
        : "r"(a0), "r"(a1), "r"(a2), "r"(a3), "r"(b0), "r"(b1))

// ---------------------------------------------------------------- prep
__global__ void prep_kernel(const float* __restrict__ phase,
                            const float* __restrict__ amp) {
    int i = blockIdx.x * 256 + threadIdx.x;
    if (i < HID) g_mod[i] = cosf(phase[i]) * amp[i];
    if (i < SQ) {
        float a = 6.283185307179586f * (float)i / (float)SQ;
        g_cs[i] = cosf(a);
        g_sn[i] = sinf(a);
    }
}

// ---------------------------------------------------------------- V roll
__global__ void roll_kernel() {
    int idx = blockIdx.x * 256 + threadIdx.x;  // float4 index
    if (idx >= BH * SQ * (HD / 4)) return;
    int d4 = idx & 15;
    int rest = idx >> 4;
    int s = rest & (SQ - 1);
    int bh = rest >> 11;
    int s2 = (s + 1) & (SQ - 1);
    const float4* v = (const float4*)g_v;
    float4 a = v[(((size_t)bh * SQ + s) << 4) + d4];
    float4 b = v[(((size_t)bh * SQ + s2) << 4) + d4];
    float4 o;
    const float r = 0.7071067811865476f;
    o.x = (a.x + b.x) * r;
    o.y = (a.y + b.y) * r;
    o.z = (a.z + b.z) * r;
    o.w = (a.w + b.w) * r;
    ((float4*)g_vp)[idx] = o;
}

// ---------------------------------------------------------------- TF32 GEMM (QKV)
// C = X[4096,1024] @ W[1024,1024], tile 128x128, kblock 32, 8 warps 2m x 4n.
// A stored in paired-k layout: within each 8-k group, order [k0,k4,k1,k5,k2,k6,k3,k7]
#define LDA 40
#define LDB 136
#define GEMM_SMEM ((2*128*LDA + 2*32*LDB) * 4)

__device__ __forceinline__ void store_a_paired(float* dst, const float4* pa) {
    float4 y0 = {tf32r(pa[0].x), tf32r(pa[1].x), tf32r(pa[0].y), tf32r(pa[1].y)};
    float4 y1 = {tf32r(pa[0].z), tf32r(pa[1].z), tf32r(pa[0].w), tf32r(pa[1].w)};
    float4 y2 = {tf32r(pa[2].x), tf32r(pa[3].x), tf32r(pa[2].y), tf32r(pa[3].y)};
    float4 y3 = {tf32r(pa[2].z), tf32r(pa[3].z), tf32r(pa[2].w), tf32r(pa[3].w)};
    *(float4*)(dst + 0) = y0;
    *(float4*)(dst + 4) = y1;
    *(float4*)(dst + 8) = y2;
    *(float4*)(dst + 12) = y3;
}

__global__ __launch_bounds__(256, 2) void qkv_gemm(const float* __restrict__ X,
                                                   const float* __restrict__ Wq,
                                                   const float* __restrict__ Wk,
                                                   const float* __restrict__ Wv) {
    extern __shared__ float smg[];
    float* As = smg;                  // [2][128*LDA] paired-k
    float* Bs = smg + 2 * 128 * LDA;  // [2][32*LDB]

    int mode = blockIdx.z;
    const float* W = (mode == 0) ? Wq : (mode == 1) ? Wk : Wv;
    float* dst = (mode == 0) ? g_q : (mode == 1) ? g_k : g_v;

    int bn = blockIdx.x, bm = blockIdx.y;
    int tid = threadIdx.x, lane = tid & 31, w = tid >> 5;
    int wm = w >> 2, wn = w & 3;
    int r = lane >> 2, c = lane & 3;

    int arow = tid >> 1, acol0 = (tid & 1) * 16;
    int brow = tid >> 3, bcol0 = (tid & 7) * 16;
    const float* Ag = X + (size_t)(bm * 128 + arow) * HID + acol0;
    const float* Bg = W + (size_t)brow * HID + bn * 128 + bcol0;

    float4 pa[4], pb[4];
#pragma unroll
    for (int q = 0; q < 4; q++) {
        pa[q] = *(const float4*)(Ag + q * 4);
        pb[q] = *(const float4*)(Bg + q * 4);
    }
    store_a_paired(&As[arow * LDA + acol0], pa);
#pragma unroll
    for (int q = 0; q < 4; q++) {
        float4 tb = {tf32r(pb[q].x), tf32r(pb[q].y), tf32r(pb[q].z), tf32r(pb[q].w)};
        *(float4*)&Bs[brow * LDB + bcol0 + q * 4] = tb;
    }
    __syncthreads();

    float acc[4][4][4];
#pragma unroll
    for (int i = 0; i < 4; i++)
#pragma unroll
        for (int j = 0; j < 4; j++)
#pragma unroll
            for (int e = 0; e < 4; e++) acc[i][j][e] = 0.f;

    for (int kb = 0; kb < 32; kb++) {
        const float* Ac = As + (kb & 1) * (128 * LDA);
        const float* Bc = Bs + (kb & 1) * (32 * LDB);
        if (kb < 31) {
            const float* Ag2 = Ag + (kb + 1) * 32;
            const float* Bg2 = Bg + (size_t)(kb + 1) * 32 * HID;
#pragma unroll
            for (int q = 0; q < 4; q++) {
                pa[q] = *(const float4*)(Ag2 + q * 4);
                pb[q] = *(const float4*)(Bg2 + q * 4);
            }
        }
#pragma unroll
        for (int kk = 0; kk < 4; kk++) {
            unsigned a[4][4], b[4][2];
#pragma unroll
            for (int i = 0; i < 4; i++) {
                const float* p = Ac + (wm * 64 + i * 16 + r) * LDA + kk * 8 + 2 * c;
                float2 lo = *(const float2*)p;
                float2 hi = *(const float2*)(p + 8 * LDA);
                a[i][0] = fu(lo.x);
                a[i][1] = fu(hi.x);
                a[i][2] = fu(lo.y);
                a[i][3] = fu(hi.y);
            }
#pragma unroll
            for (int j = 0; j < 4; j++) {
                const float* p = Bc + (kk * 8 + c) * LDB + wn * 32 + j * 8 + r;
                b[j][0] = fu(p[0]);
                b[j][1] = fu(p[4 * LDB]);
            }
#pragma unroll
            for (int i = 0; i < 4; i++)
#pragma unroll
                for (int j = 0; j < 4; j++)
                    MMA_TF32(acc[i][j], a[i][0], a[i][1], a[i][2], a[i][3],
                             b[j][0], b[j][1]);
        }
        if (kb < 31) {
            float* An = As + ((kb + 1) & 1) * (128 * LDA);
            float* Bn = Bs + ((kb + 1) & 1) * (32 * LDB);
            store_a_paired(&An[arow * LDA + acol0], pa);
#pragma unroll
            for (int q = 0; q < 4; q++) {
                float4 tb = {tf32r(pb[q].x), tf32r(pb[q].y), tf32r(pb[q].z), tf32r(pb[q].w)};
                *(float4*)&Bn[brow * LDB + bcol0 + q * 4] = tb;
            }
            __syncthreads();
        }
    }

    // epilogue: mod scale (q also 1/8), scatter to [B,H,S,D]
    float sc = (mode == 0) ? 0.125f : 1.0f;
#pragma unroll
    for (int i = 0; i < 4; i++) {
#pragma unroll
        for (int ro = 0; ro < 2; ro++) {
            int grow = bm * 128 + wm * 64 + i * 16 + r + ro * 8;
            int bb = grow >> 11;
            int ss = grow & 2047;
#pragma unroll
            for (int j = 0; j < 4; j++) {
                int col = bn * 128 + wn * 32 + j * 8 + 2 * c;
                int hh = col >> 6;
                int dd = col & 63;
                float m0v = g_mod[col] * sc;
                float m1v = g_mod[col + 1] * sc;
                float2 v;
                v.x = acc[i][j][ro * 2 + 0] * m0v;
                v.y = acc[i][j][ro * 2 + 1] * m1v;
                *(float2*)&dst[(((size_t)(bb * HEADS + hh) * SQ + ss) * HD + dd)] = v;
            }
        }
    }
}

// ---------------------------------------------------------------- TF32 GEMM (out)
__global__ __launch_bounds__(256, 2) void out_gemm(const float* __restrict__ W,
                                                   float* __restrict__ C) {
    extern __shared__ float smg[];
    float* As = smg;
    float* Bs = smg + 2 * 128 * LDA;

    int bn = blockIdx.x, bm = blockIdx.y;
    int tid = threadIdx.x, lane = tid & 31, w = tid >> 5;
    int wm = w >> 2, wn = w & 3;
    int r = lane >> 2, c = lane & 3;

    int arow = tid >> 1, acol0 = (tid & 1) * 16;
    int brow = tid >> 3, bcol0 = (tid & 7) * 16;
    const float* Ag = g_att + (size_t)(bm * 128 + arow) * HID + acol0;
    const float* Bg = W + (size_t)brow * HID + bn * 128 + bcol0;

    float4 pa[4], pb[4];
#pragma unroll
    for (int q = 0; q < 4; q++) {
        pa[q] = *(const float4*)(Ag + q * 4);
        pb[q] = *(const float4*)(Bg + q * 4);
    }
    store_a_paired(&As[arow * LDA + acol0], pa);
#pragma unroll
    for (int q = 0; q < 4; q++) {
        float4 tb = {tf32r(pb[q].x), tf32r(pb[q].y), tf32r(pb[q].z), tf32r(pb[q].w)};
        *(float4*)&Bs[brow * LDB + bcol0 + q * 4] = tb;
    }
    __syncthreads();

    float acc[4][4][4];
#pragma unroll
    for (int i = 0; i < 4; i++)
#pragma unroll
        for (int j = 0; j < 4; j++)
#pragma unroll
            for (int e = 0; e < 4; e++) acc[i][j][e] = 0.f;

    for (int kb = 0; kb < 32; kb++) {
        const float* Ac = As + (kb & 1) * (128 * LDA);
        const float* Bc = Bs + (kb & 1) * (32 * LDB);
        if (kb < 31) {
            const float* Ag2 = Ag + (kb + 1) * 32;
            const float* Bg2 = Bg + (size_t)(kb + 1) * 32 * HID;
#pragma unroll
            for (int q = 0; q < 4; q++) {
                pa[q] = *(const float4*)(Ag2 + q * 4);
                pb[q] = *(const float4*)(Bg2 + q * 4);
            }
        }
#pragma unroll
        for (int kk = 0; kk < 4; kk++) {
            unsigned a[4][4], b[4][2];
#pragma unroll
            for (int i = 0; i < 4; i++) {
                const float* p = Ac + (wm * 64 + i * 16 + r) * LDA + kk * 8 + 2 * c;
                float2 lo = *(const float2*)p;
                float2 hi = *(const float2*)(p + 8 * LDA);
                a[i][0] = fu(lo.x);
                a[i][1] = fu(hi.x);
                a[i][2] = fu(lo.y);
                a[i][3] = fu(hi.y);
            }
#pragma unroll
            for (int j = 0; j < 4; j++) {
                const float* p = Bc + (kk * 8 + c) * LDB + wn * 32 + j * 8 + r;
                b[j][0] = fu(p[0]);
                b[j][1] = fu(p[4 * LDB]);
            }
#pragma unroll
            for (int i = 0; i < 4; i++)
#pragma unroll
                for (int j = 0; j < 4; j++)
                    MMA_TF32(acc[i][j], a[i][0], a[i][1], a[i][2], a[i][3],
                             b[j][0], b[j][1]);
        }
        if (kb < 31) {
            float* An = As + ((kb + 1) & 1) * (128 * LDA);
            float* Bn = Bs + ((kb + 1) & 1) * (32 * LDB);
            store_a_paired(&An[arow * LDA + acol0], pa);
#pragma unroll
            for (int q = 0; q < 4; q++) {
                float4 tb = {tf32r(pb[q].x), tf32r(pb[q].y), tf32r(pb[q].z), tf32r(pb[q].w)};
                *(float4*)&Bn[brow * LDB + bcol0 + q * 4] = tb;
            }
            __syncthreads();
        }
    }

#pragma unroll
    for (int i = 0; i < 4; i++) {
#pragma unroll
        for (int ro = 0; ro < 2; ro++) {
            int grow = bm * 128 + wm * 64 + i * 16 + r + ro * 8;
#pragma unroll
            for (int j = 0; j < 4; j++) {
                int col = bn * 128 + wn * 32 + j * 8 + 2 * c;
                float2 v;
                v.x = acc[i][j][ro * 2 + 0];
                v.y = acc[i][j][ro * 2 + 1];
                *(float2*)&C[(size_t)grow * HID + col] = v;
            }
        }
    }
}

// ---------------------------------------------------------------- flash attention (TF32 mma, v3)
// grid (16,16,2), 256 thr = 8 warps; warp w owns rows [w*16, w*16+16).
// M-tile 128, N-tile 64 per iteration. 2 CTAs/SM.
// Paired-k layouts for Q, K, P; V stored transposed [d][n-paired].
#define LDQ 72
#define LDK 72
#define LDVT 72
#define LDP 72
#define NT 64
#define ATT_SMEM ((128*LDQ + NT*LDK + NT*LDVT + 128*LDP + 2*NT) * 4)

__global__ __launch_bounds__(256, 2) void attn_kernel() {
    extern __shared__ float sma[];
    float* Qs = sma;                  // [128][LDQ] paired-k
    float* Ks = Qs + 128 * LDQ;       // [64][LDK] paired-k
    float* Vt = Ks + NT * LDK;        // [64 d][LDVT] n-paired
    float* Ps = Vt + NT * LDVT;       // [128][LDP] paired-k (warp-private rows)
    float* cjs = Ps + 128 * LDP;      // [64]
    float* sjs = cjs + NT;            // [64]

    int m0 = blockIdx.x * 128;
    int h = blockIdx.y, b = blockIdx.z;
    int bh = b * HEADS + h;
    const float* Qg = g_q + (size_t)bh * SQ * HD;
    const float* Kg = g_k + (size_t)bh * SQ * HD;
    const float* Vg = g_vp + (size_t)bh * SQ * HD;

    int tid = threadIdx.x, lane = tid & 31, w = tid >> 5;
    int r = lane >> 2, c = lane & 3;

    // load Q tile once (paired-k): row = tid>>1, d-half = (tid&1)*32
    {
        int row = tid >> 1;
        int dh = (tid & 1) * 32;
        const float* src = Qg + (size_t)(m0 + row) * HD + dh;
        float* drow = Qs + row * LDQ + dh;
#pragma unroll
        for (int cc = 0; cc < 4; cc++) {
            float4 x0 = *(const float4*)(src + cc * 8);
            float4 x1 = *(const float4*)(src + cc * 8 + 4);
            float4 y0 = {tf32r(x0.x), tf32r(x1.x), tf32r(x0.y), tf32r(x1.y)};
            float4 y1 = {tf32r(x0.z), tf32r(x1.z), tf32r(x0.w), tf32r(x1.w)};
            *(float4*)(drow + cc * 8) = y0;
            *(float4*)(drow + cc * 8 + 4) = y1;
        }
    }

    // per-thread row trig + online-softmax state
    float cmv[2], smv[2], ms[2], ls[2];
#pragma unroll
    for (int ro = 0; ro < 2; ro++) {
        int row = m0 + w * 16 + r + ro * 8;
        cmv[ro] = g_cs[row];
        smv[ro] = g_sn[row];
        ms[ro] = -1e30f;
        ls[ro] = 0.f;
    }
    float o[8][4];
#pragma unroll
    for (int j = 0; j < 8; j++)
#pragma unroll
        for (int e = 0; e < 4; e++) o[j][e] = 0.f;

    for (int n0 = 0; n0 < SQ; n0 += NT) {
        __syncthreads();  // previous iter's reads of Ks/Vt done (also Q store on iter 0)

        // K tile (paired-k): row = tid>>2, 2 chunk-sets
        {
            int krow = tid >> 2;
            int kcb = (tid & 3) * 8;
            const float* src = Kg + (size_t)(n0 + krow) * HD;
            float* drow = Ks + krow * LDK;
#pragma unroll
            for (int hh = 0; hh < 2; hh++) {
                int db = kcb + hh * 32;
                float4 x0 = *(const float4*)(src + db);
                float4 x1 = *(const float4*)(src + db + 4);
                float4 y0 = {tf32r(x0.x), tf32r(x1.x), tf32r(x0.y), tf32r(x1.y)};
                float4 y1 = {tf32r(x0.z), tf32r(x1.z), tf32r(x0.w), tf32r(x1.w)};
                *(float4*)(drow + db) = y0;
                *(float4*)(drow + db + 4) = y1;
            }
        }
        // V tile transposed + n-paired: d = tid&63, n-groups (tid>>6), (tid>>6)+4
        {
            int d = tid & 63;
            int ng0 = tid >> 6;
            const float* src = Vg + (size_t)n0 * HD + d;
#pragma unroll
            for (int gg = 0; gg < 2; gg++) {
                int ng = ng0 + gg * 4;
                const float* s8 = src + (size_t)(ng * 8) * HD;
                float v0 = s8[0 * HD], v4 = s8[4 * HD];
                float v1 = s8[1 * HD], v5 = s8[5 * HD];
                float v2 = s8[2 * HD], v6 = s8[6 * HD];
                float v3 = s8[3 * HD], v7 = s8[7 * HD];
                float4 y0 = {tf32r(v0), tf32r(v4), tf32r(v1), tf32r(v5)};
                float4 y1 = {tf32r(v2), tf32r(v6), tf32r(v3), tf32r(v7)};
                *(float4*)(Vt + d * LDVT + ng * 8) = y0;
                *(float4*)(Vt + d * LDVT + ng * 8 + 4) = y1;
            }
        }
        if (tid < NT) {
            cjs[tid] = g_cs[n0 + tid];
            sjs[tid] = g_sn[n0 + tid];
        }
        __syncthreads();

        // S = Q K^T : warp tile m16 x n64
        float s[8][4];
#pragma unroll
        for (int j = 0; j < 8; j++)
#pragma unroll
            for (int e = 0; e < 4; e++) s[j][e] = 0.f;

#pragma unroll
        for (int kk = 0; kk < 8; kk++) {
            float2 qlo = *(const float2*)&Qs[(w * 16 + r) * LDQ + kk * 8 + 2 * c];
            float2 qhi = *(const float2*)&Qs[(w * 16 + r + 8) * LDQ + kk * 8 + 2 * c];
            unsigned a0 = fu(qlo.x), a1 = fu(qhi.x), a2 = fu(qlo.y), a3 = fu(qhi.y);
#pragma unroll
            for (int j = 0; j < 8; j++) {
                float2 kb = *(const float2*)&Ks[(j * 8 + r) * LDK + kk * 8 + 2 * c];
                MMA_TF32(s[j], a0, a1, a2, a3, fu(kb.x), fu(kb.y));
            }
        }

        // interference modulation
#pragma unroll
        for (int j = 0; j < 8; j++) {
            float2 cjp = *(const float2*)&cjs[j * 8 + 2 * c];
            float2 sjp = *(const float2*)&sjs[j * 8 + 2 * c];
            s[j][0] *= (cmv[0] * cjp.x + smv[0] * sjp.x);
            s[j][1] *= (cmv[0] * cjp.y + smv[0] * sjp.y);
            s[j][2] *= (cmv[1] * cjp.x + smv[1] * sjp.x);
            s[j][3] *= (cmv[1] * cjp.y + smv[1] * sjp.y);
        }

        // online softmax per row group
#pragma unroll
        for (int ro = 0; ro < 2; ro++) {
            float mx = -1e30f;
#pragma unroll
            for (int j = 0; j < 8; j++)
                mx = fmaxf(mx, fmaxf(s[j][ro * 2], s[j][ro * 2 + 1]));
            mx = fmaxf(mx, __shfl_xor_sync(0xffffffffu, mx, 1));
            mx = fmaxf(mx, __shfl_xor_sync(0xffffffffu, mx, 2));
            float mn = fmaxf(ms[ro], mx);
            float al = __expf(ms[ro] - mn);
            float sum = 0.f;
#pragma unroll
            for (int j = 0; j < 8; j++) {
                float p0 = __expf(s[j][ro * 2] - mn);
                float p1 = __expf(s[j][ro * 2 + 1] - mn);
                s[j][ro * 2] = p0;
                s[j][ro * 2 + 1] = p1;
                sum += p0 + p1;
            }
            sum += __shfl_xor_sync(0xffffffffu, sum, 1);
            sum += __shfl_xor_sync(0xffffffffu, sum, 2);
            ls[ro] = ls[ro] * al + sum;
            ms[ro] = mn;
#pragma unroll
            for (int j2 = 0; j2 < 8; j2++) {
                o[j2][ro * 2] *= al;
                o[j2][ro * 2 + 1] *= al;
            }
        }

        // write P (warp-private rows, paired-k positions)
        {
            int p0 = (c < 2) ? 4 * c : 4 * c - 7;
            int p1 = (c < 2) ? 4 * c + 2 : 4 * c - 5;
            float* pr = Ps + (w * 16 + r) * LDP;
#pragma unroll
            for (int j = 0; j < 8; j++) {
                float* pj = pr + j * 8;
                pj[p0] = tf32r(s[j][0]);
                pj[p1] = tf32r(s[j][1]);
                pj[8 * LDP + p0] = tf32r(s[j][2]);
                pj[8 * LDP + p1] = tf32r(s[j][3]);
            }
        }
        __syncwarp();

        // O += P @ V' : warp tile m16 x n64, k = NT
#pragma unroll
        for (int kk = 0; kk < 8; kk++) {
            float2 plo = *(const float2*)&Ps[(w * 16 + r) * LDP + kk * 8 + 2 * c];
            float2 phi = *(const float2*)&Ps[(w * 16 + r + 8) * LDP + kk * 8 + 2 * c];
            unsigned a0 = fu(plo.x), a1 = fu(phi.x), a2 = fu(plo.y), a3 = fu(phi.y);
#pragma unroll
            for (int j2 = 0; j2 < 8; j2++) {
                float2 bv = *(const float2*)&Vt[(j2 * 8 + r) * LDVT + kk * 8 + 2 * c];
                MMA_TF32(o[j2], a0, a1, a2, a3, fu(bv.x), fu(bv.y));
            }
        }
        __syncwarp();  // P reads done before next iter's P stores
    }

    // epilogue: normalize + write [B,S,H*D]
#pragma unroll
    for (int ro = 0; ro < 2; ro++) {
        float inv = 1.0f / ls[ro];
        int row = m0 + w * 16 + r + ro * 8;
#pragma unroll
        for (int j2 = 0; j2 < 8; j2++) {
            int col = j2 * 8 + 2 * c;
            float2 v;
            v.x = o[j2][ro * 2] * inv;
            v.y = o[j2][ro * 2 + 1] * inv;
            *(float2*)&g_att[((size_t)(b * SQ + row)) * HID + h * HD + col] = v;
        }
    }
}

// ---------------------------------------------------------------- launch
extern "C" void kernel_launch(void* const* d_in, const int* in_sizes, int n_in,
                              void* d_out, int out_size) {
    const float* x     = (const float*)d_in[0];
    const float* Wq    = (const float*)d_in[1];
    const float* Wk    = (const float*)d_in[2];
    const float* Wv    = (const float*)d_in[3];
    const float* Wo    = (const float*)d_in[4];
    const float* phase = (const float*)d_in[5];
    const float* amp   = (const float*)d_in[6];
    float* out = (float*)d_out;

    cudaFuncSetAttribute(qkv_gemm, cudaFuncAttributeMaxDynamicSharedMemorySize, GEMM_SMEM);
    cudaFuncSetAttribute(out_gemm, cudaFuncAttributeMaxDynamicSharedMemorySize, GEMM_SMEM);
    cudaFuncSetAttribute(attn_kernel, cudaFuncAttributeMaxDynamicSharedMemorySize, ATT_SMEM);

    prep_kernel<<<8, 256>>>(phase, amp);
    qkv_gemm<<<dim3(8, 32, 3), 256, GEMM_SMEM>>>(x, Wq, Wk, Wv);
    roll_kernel<<<(BH * SQ * (HD / 4)) / 256, 256>>>();
    attn_kernel<<<dim3(16, 16, 2), 256, ATT_SMEM>>>();
    out_gemm<<<dim3(8, 32), 256, GEMM_SMEM>>>(Wo, out);
}

// round 6
// speedup vs baseline: 2.2370x; 2.2317x over previous
#include <cuda_runtime.h>
#include <cuda_fp16.h>

#define SQ 2048
#define HID 1024
#define HEADS 16
#define HD 64
#define BSZ 2
#define BH (BSZ*HEADS)
#define ROWS_TOT (BSZ*SQ)
#define LOG2E 1.44269504f
#define SHF 8.65617025f  /* 6*log2(e); fixed softmax shift, cancels in O/l */

__device__ __half g_xh[ROWS_TOT*HID];
__device__ __half g_wt[4*HID*HID];     // W^T [n][k] fp16, 4 mats
__device__ __half g_q[BH*SQ*HD];       // mod*0.125 folded
__device__ __half g_k[BH*SQ*HD];       // mod folded
__device__ __half g_v[BH*SQ*HD];
__device__ __half g_vt[BH*HD*SQ];      // rolled V transposed [bh][d][n]
__device__ __half g_att[ROWS_TOT*HID];
__device__ float g_mod[HID];
__device__ float g_cs[SQ];
__device__ float g_sn[SQ];

__device__ __forceinline__ unsigned su(const void* p) {
    return (unsigned)__cvta_generic_to_shared(p);
}
__device__ __forceinline__ float ex2(float x) {
    float y;
    asm("ex2.approx.ftz.f32 %0, %1;" : "=f"(y) : "f"(x));
    return y;
}
__device__ __forceinline__ unsigned pk(float a, float b) {
    __half2 h = __floats2half2_rn(a, b);
    return *(unsigned*)&h;
}

#define LDSM4(R0,R1,R2,R3,A)                                                    \
    asm volatile("ldmatrix.sync.aligned.m8n8.x4.shared.b16 {%0,%1,%2,%3},[%4];" \
                 : "=r"(R0), "=r"(R1), "=r"(R2), "=r"(R3) : "r"(A))
#define HMMA(D,A0,A1,A2,A3,B0,B1)                                               \
    asm volatile("mma.sync.aligned.m16n8k16.row.col.f32.f16.f16.f32 "           \
                 "{%0,%1,%2,%3},{%4,%5,%6,%7},{%8,%9},{%0,%1,%2,%3};"           \
                 : "+f"(D[0]), "+f"(D[1]), "+f"(D[2]), "+f"(D[3])               \
                 : "r"(A0), "r"(A1), "r"(A2), "r"(A3), "r"(B0), "r"(B1))
#define CP16(D,S) asm volatile("cp.async.cg.shared.global [%0],[%1],16;" :: "r"(D), "l"(S))
#define CPC()     asm volatile("cp.async.commit_group;")

// ---------------------------------------------------------------- prep
__global__ void prep_kernel(const float* __restrict__ phase,
                            const float* __restrict__ amp) {
    int i = blockIdx.x * 256 + threadIdx.x;
    if (i < HID) g_mod[i] = cosf(phase[i]) * amp[i];
    if (i < SQ) {
        float a = 6.283185307179586f * (float)i / (float)SQ;
        g_cs[i] = cosf(a);
        g_sn[i] = sinf(a);
    }
}

__global__ void convert_x(const float* __restrict__ x) {
    int i = (blockIdx.x * 256 + threadIdx.x) * 8;
    float4 f0 = *(const float4*)(x + i);
    float4 f1 = *(const float4*)(x + i + 4);
    __half2* o = (__half2*)(g_xh + i);
    o[0] = __floats2half2_rn(f0.x, f0.y);
    o[1] = __floats2half2_rn(f0.z, f0.w);
    o[2] = __floats2half2_rn(f1.x, f1.y);
    o[3] = __floats2half2_rn(f1.z, f1.w);
}

__global__ void transpose_w(const float* __restrict__ Wq, const float* __restrict__ Wk,
                            const float* __restrict__ Wv, const float* __restrict__ Wo) {
    __shared__ float t[32][33];
    int z = blockIdx.z;
    const float* W = (z == 0) ? Wq : (z == 1) ? Wk : (z == 2) ? Wv : Wo;
    int n0 = blockIdx.x * 32, k0 = blockIdx.y * 32;
    int tx = threadIdx.x, ty = threadIdx.y;
#pragma unroll
    for (int i = 0; i < 4; i++)
        t[ty + i * 8][tx] = W[(size_t)(k0 + ty + i * 8) * HID + n0 + tx];
    __syncthreads();
    __half* dst = g_wt + (size_t)z * HID * HID;
#pragma unroll
    for (int i = 0; i < 4; i++)
        dst[(size_t)(n0 + ty + i * 8) * HID + k0 + tx] = __float2half_rn(t[tx][ty + i * 8]);
}

// ---------------------------------------------------------------- roll + transpose V
__global__ __launch_bounds__(256) void roll_t_kernel() {
    __shared__ __half ts[65][72];
    int n0 = blockIdx.x * 64, bh = blockIdx.y, tid = threadIdx.x;
    int rr = tid >> 2, seg = (tid & 3) * 16;
    const __half* src = g_v + ((size_t)bh * SQ + n0 + rr) * HD + seg;
    *(uint4*)&ts[rr][seg] = *(const uint4*)src;
    *(uint4*)&ts[rr][seg + 8] = *(const uint4*)(src + 8);
    if (tid < 4) {
        int nz = (n0 + 64) & (SQ - 1);
        const __half* s2 = g_v + ((size_t)bh * SQ + nz) * HD + tid * 16;
        *(uint4*)&ts[64][tid * 16] = *(const uint4*)s2;
        *(uint4*)&ts[64][tid * 16 + 8] = *(const uint4*)(s2 + 8);
    }
    __syncthreads();
    int d = tid >> 2, ns = (tid & 3) * 16;
    const float R = 0.7071067811865476f;
    __half2 ov[8];
#pragma unroll
    for (int i = 0; i < 8; i++) {
        int n = ns + 2 * i;
        float a = __half2float(ts[n][d]);
        float b = __half2float(ts[n + 1][d]);
        float c = __half2float(ts[n + 2][d]);
        ov[i] = __floats2half2_rn((a + b) * R, (b + c) * R);
    }
    __half* dst = g_vt + ((size_t)bh * HD + d) * SQ + n0 + ns;
    *(uint4*)dst = *(uint4*)&ov[0];
    *(uint4*)(dst + 8) = *(uint4*)&ov[4];
}

// ---------------------------------------------------------------- fp16 GEMM core
// C[128,128] = A[.,1024] @ B^T ; 512 thr = 16 warps (4m x 4n), warp m32 x n32.
// smem rows 32 halves + 8 pad (80B) -> ldmatrix conflict-free.
__device__ __forceinline__ void gemm_core(const __half* Arow0, const __half* Brow0,
                                          float (&acc)[2][4][4]) {
    extern __shared__ __half sm[];
    __half* As = sm;               // [2][128][40]
    __half* Bs = sm + 2 * 128 * 40;
    int tid = threadIdx.x, lane = tid & 31, w = tid >> 5;
    int wm = w >> 2, wn = w & 3;
    int lrow = tid >> 2, lseg = (tid & 3) * 8;

    const __half* sa = Arow0 + (size_t)lrow * HID + lseg;
    const __half* sb = Brow0 + (size_t)lrow * HID + lseg;
    unsigned da = su(As + lrow * 40 + lseg);
    unsigned db = su(Bs + lrow * 40 + lseg);

    CP16(da, sa); CP16(db, sb); CPC();

    int arow = wm * 32 + (lane & 15);
    int brow = wn * 32 + (lane & 15);
    int coff = (lane >> 4) * 8;

    for (int st = 0; st < 32; st++) {
        int buf = st & 1;
        if (st < 31) {
            int nb = (st + 1) & 1;
            CP16(da + nb * 128 * 80, sa + (st + 1) * 32);
            CP16(db + nb * 128 * 80, sb + (st + 1) * 32);
            CPC();
            asm volatile("cp.async.wait_group 1;");
        } else {
            asm volatile("cp.async.wait_group 0;");
        }
        __syncthreads();
        const __half* Ac = As + buf * 128 * 40;
        const __half* Bc = Bs + buf * 128 * 40;
#pragma unroll
        for (int kk = 0; kk < 2; kk++) {
            unsigned au[2][4], bu[2][4];
#pragma unroll
            for (int i = 0; i < 2; i++)
                LDSM4(au[i][0], au[i][1], au[i][2], au[i][3],
                      su(Ac + (arow + i * 16) * 40 + kk * 16 + coff));
#pragma unroll
            for (int jp = 0; jp < 2; jp++)
                LDSM4(bu[jp][0], bu[jp][1], bu[jp][2], bu[jp][3],
                      su(Bc + (brow + jp * 16) * 40 + kk * 16 + coff));
#pragma unroll
            for (int i = 0; i < 2; i++)
#pragma unroll
                for (int j = 0; j < 4; j++)
                    HMMA(acc[i][j], au[i][0], au[i][1], au[i][2], au[i][3],
                         bu[j >> 1][j & 1], bu[j >> 1][2 + (j & 1)]);
        }
        __syncthreads();
    }
}

__global__ __launch_bounds__(512) void qkv_gemm() {
    int mode = blockIdx.z;
    float acc[2][4][4];
#pragma unroll
    for (int i = 0; i < 2; i++)
#pragma unroll
        for (int j = 0; j < 4; j++)
#pragma unroll
            for (int e = 0; e < 4; e++) acc[i][j][e] = 0.f;
    int bm = blockIdx.y, bn = blockIdx.x;
    gemm_core(g_xh + (size_t)bm * 128 * HID, g_wt + (size_t)mode * HID * HID + (size_t)bn * 128 * HID, acc);

    __half* dst = (mode == 0) ? g_q : (mode == 1) ? g_k : g_v;
    float sc = (mode == 0) ? 0.125f : 1.0f;
    int tid = threadIdx.x, lane = tid & 31, w = tid >> 5;
    int wm = w >> 2, wn = w & 3, r = lane >> 2, c = lane & 3;
#pragma unroll
    for (int i = 0; i < 2; i++) {
#pragma unroll
        for (int ro = 0; ro < 2; ro++) {
            int grow = bm * 128 + wm * 32 + i * 16 + r + ro * 8;
            int bb = grow >> 11, ss = grow & 2047;
#pragma unroll
            for (int j = 0; j < 4; j++) {
                int col = bn * 128 + wn * 32 + j * 8 + 2 * c;
                int hh = col >> 6, dd = col & 63;
                float m0 = g_mod[col] * sc, m1 = g_mod[col + 1] * sc;
                __half2 v = __floats2half2_rn(acc[i][j][ro * 2] * m0,
                                              acc[i][j][ro * 2 + 1] * m1);
                *(__half2*)&dst[(((size_t)(bb * HEADS + hh) * SQ + ss) * HD + dd)] = v;
            }
        }
    }
}

__global__ __launch_bounds__(512) void out_gemm(float* __restrict__ C) {
    float acc[2][4][4];
#pragma unroll
    for (int i = 0; i < 2; i++)
#pragma unroll
        for (int j = 0; j < 4; j++)
#pragma unroll
            for (int e = 0; e < 4; e++) acc[i][j][e] = 0.f;
    int bm = blockIdx.y, bn = blockIdx.x;
    gemm_core(g_att + (size_t)bm * 128 * HID, g_wt + (size_t)3 * HID * HID + (size_t)bn * 128 * HID, acc);

    int tid = threadIdx.x, lane = tid & 31, w = tid >> 5;
    int wm = w >> 2, wn = w & 3, r = lane >> 2, c = lane & 3;
#pragma unroll
    for (int i = 0; i < 2; i++) {
#pragma unroll
        for (int ro = 0; ro < 2; ro++) {
            int grow = bm * 128 + wm * 32 + i * 16 + r + ro * 8;
#pragma unroll
            for (int j = 0; j < 4; j++) {
                int col = bn * 128 + wn * 32 + j * 8 + 2 * c;
                float2 v = {acc[i][j][ro * 2], acc[i][j][ro * 2 + 1]};
                *(float2*)&C[(size_t)grow * HID + col] = v;
            }
        }
    }
}

// ---------------------------------------------------------------- flash attention fp16
// grid (16,16,2), 256 thr = 8 warps, warp owns rows [w*16, w*16+16); N-tile 64.
__global__ __launch_bounds__(256, 2) void attn_kernel() {
    __shared__ __half Qs[128 * 72], Ks[64 * 72], Vts[64 * 72];
    __shared__ float cjs[64], sjs[64];

    int m0 = blockIdx.x * 128, h = blockIdx.y, b = blockIdx.z;
    int bh = b * HEADS + h;
    const __half* Qg = g_q + (size_t)bh * SQ * HD;
    const __half* Kg = g_k + (size_t)bh * SQ * HD;
    const __half* Vg = g_vt + (size_t)bh * HD * SQ;

    int tid = threadIdx.x, lane = tid & 31, w = tid >> 5;
    int r = lane >> 2, c = lane & 3;

    {   // load Q tile once
        int row = tid >> 1, seg = (tid & 1) * 32;
        const uint4* s = (const uint4*)(Qg + (size_t)(m0 + row) * HD + seg);
        uint4* d = (uint4*)(Qs + row * 72 + seg);
        d[0] = s[0]; d[1] = s[1]; d[2] = s[2]; d[3] = s[3];
    }
    __syncthreads();

    unsigned qa[4][4];
#pragma unroll
    for (int kk = 0; kk < 4; kk++)
        LDSM4(qa[kk][0], qa[kk][1], qa[kk][2], qa[kk][3],
              su(Qs + (w * 16 + (lane & 15)) * 72 + kk * 16 + (lane >> 4) * 8));

    float cm0, sm0, cm1, sm1;  // premultiplied by LOG2E
    {
        int row = m0 + w * 16 + r;
        cm0 = g_cs[row] * LOG2E; sm0 = g_sn[row] * LOG2E;
        cm1 = g_cs[row + 8] * LOG2E; sm1 = g_sn[row + 8] * LOG2E;
    }
    float l0 = 0.f, l1 = 0.f;
    float o[8][4];
#pragma unroll
    for (int j = 0; j < 8; j++)
#pragma unroll
        for (int e = 0; e < 4; e++) o[j][e] = 0.f;

    int krow = tid >> 2, kseg = (tid & 3) * 16;

    for (int n0 = 0; n0 < SQ; n0 += 64) {
        __syncthreads();
        {
            const __half* sk = Kg + (size_t)(n0 + krow) * HD + kseg;
            *(uint4*)(Ks + krow * 72 + kseg) = *(const uint4*)sk;
            *(uint4*)(Ks + krow * 72 + kseg + 8) = *(const uint4*)(sk + 8);
            const __half* sv = Vg + (size_t)krow * SQ + n0 + kseg;
            *(uint4*)(Vts + krow * 72 + kseg) = *(const uint4*)sv;
            *(uint4*)(Vts + krow * 72 + kseg + 8) = *(const uint4*)(sv + 8);
            if (tid < 64) { cjs[tid] = g_cs[n0 + tid]; sjs[tid] = g_sn[n0 + tid]; }
        }
        __syncthreads();

        // S = Q K^T (m16 x n64)
        float s[8][4];
#pragma unroll
        for (int j = 0; j < 8; j++)
#pragma unroll
            for (int e = 0; e < 4; e++) s[j][e] = 0.f;
#pragma unroll
        for (int kk = 0; kk < 4; kk++) {
#pragma unroll
            for (int jp = 0; jp < 4; jp++) {
                unsigned b0, b1, b2, b3;
                LDSM4(b0, b1, b2, b3,
                      su(Ks + (jp * 16 + (lane & 15)) * 72 + kk * 16 + (lane >> 4) * 8));
                HMMA(s[2 * jp], qa[kk][0], qa[kk][1], qa[kk][2], qa[kk][3], b0, b2);
                HMMA(s[2 * jp + 1], qa[kk][0], qa[kk][1], qa[kk][2], qa[kk][3], b1, b3);
            }
        }

        // interference + exp(s-6) + l accumulation, pack to fp16 A-frags
        unsigned pf[4][4];
#pragma unroll
        for (int j = 0; j < 8; j++) {
            float2 cj = *(float2*)&cjs[j * 8 + 2 * c];
            float2 sj = *(float2*)&sjs[j * 8 + 2 * c];
            float w00 = cm0 * cj.x + sm0 * sj.x;
            float w01 = cm0 * cj.y + sm0 * sj.y;
            float w10 = cm1 * cj.x + sm1 * sj.x;
            float w11 = cm1 * cj.y + sm1 * sj.y;
            s[j][0] = ex2(fmaf(s[j][0], w00, -SHF));
            s[j][1] = ex2(fmaf(s[j][1], w01, -SHF));
            s[j][2] = ex2(fmaf(s[j][2], w10, -SHF));
            s[j][3] = ex2(fmaf(s[j][3], w11, -SHF));
            l0 += s[j][0] + s[j][1];
            l1 += s[j][2] + s[j][3];
        }
#pragma unroll
        for (int kk = 0; kk < 4; kk++) {
            pf[kk][0] = pk(s[2 * kk][0], s[2 * kk][1]);
            pf[kk][1] = pk(s[2 * kk][2], s[2 * kk][3]);
            pf[kk][2] = pk(s[2 * kk + 1][0], s[2 * kk + 1][1]);
            pf[kk][3] = pk(s[2 * kk + 1][2], s[2 * kk + 1][3]);
        }

        // O += P @ V' (m16 x d64, k=n64)
#pragma unroll
        for (int kk = 0; kk < 4; kk++) {
#pragma unroll
            for (int jp = 0; jp < 4; jp++) {
                unsigned b0, b1, b2, b3;
                LDSM4(b0, b1, b2, b3,
                      su(Vts + (jp * 16 + (lane & 15)) * 72 + kk * 16 + (lane >> 4) * 8));
                HMMA(o[2 * jp], pf[kk][0], pf[kk][1], pf[kk][2], pf[kk][3], b0, b2);
                HMMA(o[2 * jp + 1], pf[kk][0], pf[kk][1], pf[kk][2], pf[kk][3], b1, b3);
            }
        }
    }

    l0 += __shfl_xor_sync(0xffffffffu, l0, 1);
    l0 += __shfl_xor_sync(0xffffffffu, l0, 2);
    l1 += __shfl_xor_sync(0xffffffffu, l1, 1);
    l1 += __shfl_xor_sync(0xffffffffu, l1, 2);
    float i0 = 1.0f / l0, i1 = 1.0f / l1;

    int row0 = b * SQ + m0 + w * 16 + r;
#pragma unroll
    for (int j = 0; j < 8; j++) {
        int col = h * HD + j * 8 + 2 * c;
        *(__half2*)&g_att[(size_t)row0 * HID + col] =
            __floats2half2_rn(o[j][0] * i0, o[j][1] * i0);
        *(__half2*)&g_att[(size_t)(row0 + 8) * HID + col] =
            __floats2half2_rn(o[j][2] * i1, o[j][3] * i1);
    }
}

// ---------------------------------------------------------------- launch
extern "C" void kernel_launch(void* const* d_in, const int* in_sizes, int n_in,
                              void* d_out, int out_size) {
    const float* x     = (const float*)d_in[0];
    const float* Wq    = (const float*)d_in[1];
    const float* Wk    = (const float*)d_in[2];
    const float* Wv    = (const float*)d_in[3];
    const float* Wo    = (const float*)d_in[4];
    const float* phase = (const float*)d_in[5];
    const float* amp   = (const float*)d_in[6];
    float* out = (float*)d_out;

    const int GS = 2 * 128 * 40 * 2 * 2;  // 40960 B dynamic smem for GEMMs

    prep_kernel<<<8, 256>>>(phase, amp);
    convert_x<<<ROWS_TOT * HID / (256 * 8), 256>>>(x);
    transpose_w<<<dim3(32, 32, 4), dim3(32, 8)>>>(Wq, Wk, Wv, Wo);
    qkv_gemm<<<dim3(8, 32, 3), 512, GS>>>();
    roll_t_kernel<<<dim3(SQ / 64, BH), 256>>>();
    attn_kernel<<<dim3(16, 16, 2), 256>>>();
    out_gemm<<<dim3(8, 32), 512, GS>>>(out);
}